// round 5
// baseline (speedup 1.0000x reference)
#include <cuda_runtime.h>
#include <math.h>

#define IMG_W   1920
#define BX      128
#define TILE_F4 34            // float4 per smem row: cols [u0-4, u0+131]
#define TILE_W  (TILE_F4 * 4)

// ---- frozen per-pixel math: bit-exact vs reference; DO NOT TOUCH ----
__device__ __forceinline__ void compute_pixel(
    int u, int v, int H, float z,
    const float* __restrict__ ref_img,
    float tc,   // trg_img[v*W+u]
    float tA, float tB, float tC, float tD, float tE, float tF, float tG, float tH,
    float R00, float R01, float R02, float R10, float R11, float R12,
    float R20, float R21, float R22, float t0, float t1, float t2v,
    float fx, float fy, float cx, float cy,
    float* o)
{
    o[0] = 0.f; o[1] = 0.f; o[2] = 0.f; o[3] = 0.f; o[4] = 0.f; o[5] = 0.f; o[6] = 0.f;

    const float px = __fdiv_rn(__fmul_rn((float)u - cx, z), fx);
    const float py = __fdiv_rn(__fmul_rn((float)v - cy, z), fy);
    const float pz = z;

    const float q0 = __fadd_rn(__fmaf_rn(pz, R02, __fmaf_rn(py, R01, __fmul_rn(px, R00))), t0);
    const float q1 = __fadd_rn(__fmaf_rn(pz, R12, __fmaf_rn(py, R11, __fmul_rn(px, R10))), t1);
    const float q2 = __fadd_rn(__fmaf_rn(pz, R22, __fmaf_rn(py, R21, __fmul_rn(px, R20))), t2v);

    // proj = p @ K.T : NON-FUSED mul + add (matches reference rounding)
    const float pr0 = __fadd_rn(__fmul_rn(q0, fx), __fmul_rn(q2, cx));
    const float pr1 = __fadd_rn(__fmul_rn(q1, fy), __fmul_rn(q2, cy));

    const float uw = __fdiv_rn(pr0, q2);
    const float vw = __fdiv_rn(pr1, q2);
    const int ui = __float2int_rz(uw);
    const int vi = __float2int_rz(vw);

    const bool valid = (vi < H) && (ui < IMG_W) && (vi > 0) && (ui > 0);
    if (!valid) return;

    const float warped = __ldg(&ref_img[vi * IMG_W + ui]);
    o[0] = __fsub_rn(warped, tc);

    if (u >= 2 && u < IMG_W - 2 && v >= 2 && v < H - 2) {
        const float gx = 0.125f * (tC - tA) + 0.25f * (tE - tD) + 0.125f * (tH - tF);
        const float gy = 0.125f * (tF - tA) + 0.25f * (tG - tB) + 0.125f * (tH - tC);

        const float zi  = __fdividef(1.0f, pz);    // J path: approx ok
        const float xzi = px * zi;
        const float yzi = py * zi;
        const float fgx = fx * gx;                 // reference uses fx for BOTH rows
        const float fgy = fx * gy;

        o[1] = -(fgx * (xzi * yzi) + fgy * (1.0f + yzi * yzi));
        o[2] =   fgx * (1.0f + xzi * xzi) + fgy * (xzi * yzi);
        o[3] =   fgy * xzi - fgx * yzi;
        o[4] =   fgx * zi;
        o[5] =   fgy * zi;
        o[6] = -(fgx * xzi + fgy * yzi) * zi;
    }
}

__global__ __launch_bounds__(BX, 9) void pose_kernel(
    const float* __restrict__ ref_img,
    const float* __restrict__ ref_depth,
    const float* __restrict__ trg_img,
    const float* __restrict__ xv,
    const float* __restrict__ K,
    float* __restrict__ out,
    int H)
{
    __shared__ float st[4][TILE_W];      // trg rows v0-1 .. v0+2
    __shared__ float so[2 * BX * 7];     // output staging (2 rows)
    __shared__ float spp[16];            // R[9], t[3], fx, fy, cx, cy

    const int tid = threadIdx.x;
    const int u0  = blockIdx.x * BX;
    const int v0  = blockIdx.y * 2;
    const int u   = u0 + tid;

    // ---- thread 0: SE(3) exp + intrinsics (exact for x=0: R=I, t=0) ----
    if (tid == 0) {
        float wx = xv[0], wy = xv[1], wz = xv[2];
        float vx = xv[3], vy = xv[4], vz = xv[5];
        float t2 = wx * wx + wy * wy + wz * wz;
        bool small = t2 < 1e-8f;
        float th = sqrtf(small ? 1.0f : t2);
        float A = small ? (1.0f - t2 / 6.0f) : (sinf(th) / th);
        float B = small ? (0.5f - t2 / 24.0f) : ((1.0f - cosf(th)) / (th * th));
        float C = small ? (1.0f / 6.0f - t2 / 120.0f) : ((th - sinf(th)) / (th * th * th));
        float W[9] = {0.f, -wz, wy,  wz, 0.f, -wx,  -wy, wx, 0.f};
        float W2[9];
        #pragma unroll
        for (int i = 0; i < 3; i++)
            #pragma unroll
            for (int j = 0; j < 3; j++) {
                float s = 0.f;
                #pragma unroll
                for (int k = 0; k < 3; k++) s += W[i * 3 + k] * W[k * 3 + j];
                W2[i * 3 + j] = s;
            }
        float V[9];
        #pragma unroll
        for (int i = 0; i < 9; i++) {
            float id = (i % 4 == 0) ? 1.f : 0.f;
            spp[i] = id + A * W[i] + B * W2[i];
            V[i]   = id + B * W[i] + C * W2[i];
        }
        spp[9]  = V[0] * vx + V[1] * vy + V[2] * vz;
        spp[10] = V[3] * vx + V[4] * vy + V[5] * vz;
        spp[11] = V[6] * vx + V[7] * vy + V[8] * vz;
        spp[12] = K[0]; spp[13] = K[4]; spp[14] = K[2]; spp[15] = K[5];
    }

    // ---- cooperative trg tile load: 4 rows x 34 float4 ----
    #pragma unroll
    for (int idx = tid; idx < 4 * TILE_F4; idx += BX) {
        const int r  = idx / TILE_F4;
        const int c  = idx - r * TILE_F4;
        int gr = v0 + r - 1;
        gr = min(max(gr, 0), H - 1);           // clamped rows only feed zeroed-J border lanes
        const int gc = u0 - 4 + c * 4;
        float4 val = make_float4(0.f, 0.f, 0.f, 0.f);
        if (gc >= 0 && gc + 3 < IMG_W)
            val = *reinterpret_cast<const float4*>(trg_img + gr * IMG_W + gc);
        *reinterpret_cast<float4*>(&st[r][c * 4]) = val;
    }
    __syncthreads();

    const float R00 = spp[0], R01 = spp[1], R02 = spp[2];
    const float R10 = spp[3], R11 = spp[4], R12 = spp[5];
    const float R20 = spp[6], R21 = spp[7], R22 = spp[8];
    const float t0 = spp[9], t1 = spp[10], t2v = spp[11];
    const float fx = spp[12], fy = spp[13], cx = spp[14], cy = spp[15];

    // ---- shared Sobel taps for both rows: 12 LDS serve 2 pixels ----
    const int cm = tid + 3;
    const float r0m = st[0][cm], r0c = st[0][cm + 1], r0p = st[0][cm + 2];
    const float r1m = st[1][cm], r1c = st[1][cm + 1], r1p = st[1][cm + 2];
    const float r2m = st[2][cm], r2c = st[2][cm + 1], r2p = st[2][cm + 2];
    const float r3m = st[3][cm], r3c = st[3][cm + 1], r3p = st[3][cm + 2];

    const float z0 = __ldg(&ref_depth[(size_t)v0 * IMG_W + u]);
    const float z1 = __ldg(&ref_depth[(size_t)(v0 + 1) * IMG_W + u]);

    float oa[7], ob[7];
    compute_pixel(u, v0,     H, z0, ref_img, r1c,
                  r0m, r0c, r0p, r1m, r1p, r2m, r2c, r2p,
                  R00, R01, R02, R10, R11, R12, R20, R21, R22, t0, t1, t2v,
                  fx, fy, cx, cy, oa);
    compute_pixel(u, v0 + 1, H, z1, ref_img, r2c,
                  r1m, r1c, r1p, r2m, r2p, r3m, r3c, r3p,
                  R00, R01, R02, R10, R11, R12, R20, R21, R22, t0, t1, t2v,
                  fx, fy, cx, cy, ob);

    // ---- stage (stride-7: conflict-free) ----
    const int sa = tid * 7;
    #pragma unroll
    for (int j = 0; j < 7; j++) so[sa + j] = oa[j];
    const int sb = (BX + tid) * 7;
    #pragma unroll
    for (int j = 0; j < 7; j++) so[sb + j] = ob[j];
    __syncthreads();

    // ---- coalesced streaming float4 stores: 2 row-regions of 224 float4 ----
    const float4* s4 = (const float4*)so;
    float4* out0 = (float4*)(out + ((size_t)v0 * IMG_W + u0) * 7);
    float4* out1 = (float4*)(out + ((size_t)(v0 + 1) * IMG_W + u0) * 7);
    #pragma unroll
    for (int k = 0; k < 4; k++) {
        const int idx = tid + k * BX;          // 0 .. 447 (last iter: 64 threads)
        if (idx < 448) {
            const float4 val = s4[idx];
            if (idx < 224) __stcs(&out0[idx], val);
            else           __stcs(&out1[idx - 224], val);
        }
    }
}

extern "C" void kernel_launch(void* const* d_in, const int* in_sizes, int n_in,
                              void* d_out, int out_size) {
    const float* x         = (const float*)d_in[0];
    const float* ref_img   = (const float*)d_in[1];
    const float* ref_depth = (const float*)d_in[2];
    const float* trg_img   = (const float*)d_in[3];
    const float* K         = (const float*)d_in[4];

    const int N = in_sizes[1];          // H*W
    const int H = N / IMG_W;            // W fixed at 1920

    dim3 grid(IMG_W / BX, H / 2);
    pose_kernel<<<grid, BX>>>(ref_img, ref_depth, trg_img, x, K, (float*)d_out, H);
}

// round 6
// speedup vs baseline: 1.0819x; 1.0819x over previous
#include <cuda_runtime.h>
#include <math.h>

#define IMG_W   1920
#define BX      128
#define TILE_F4 34            // float4 per smem row: covers cols [u0-4, u0+131]
#define TILE_W  (TILE_F4 * 4)

// Params: R[9], t[3], fx, fy, cx, cy  -> 16 floats, 4x float4
struct __align__(16) PoseParams {
    float R[9];
    float t[3];
    float fx, fy, cx, cy;
};

__device__ PoseParams g_pp;

__global__ void prep_kernel(const float* __restrict__ x, const float* __restrict__ K) {
    float wx = x[0], wy = x[1], wz = x[2];
    float vx = x[3], vy = x[4], vz = x[5];
    float t2 = wx * wx + wy * wy + wz * wz;
    bool small = t2 < 1e-8f;
    float th = sqrtf(small ? 1.0f : t2);
    float A = small ? (1.0f - t2 / 6.0f) : (sinf(th) / th);
    float B = small ? (0.5f - t2 / 24.0f) : ((1.0f - cosf(th)) / (th * th));
    float C = small ? (1.0f / 6.0f - t2 / 120.0f) : ((th - sinf(th)) / (th * th * th));

    float W[9] = {0.f, -wz, wy,
                  wz, 0.f, -wx,
                  -wy, wx, 0.f};
    float W2[9];
    #pragma unroll
    for (int i = 0; i < 3; i++)
        #pragma unroll
        for (int j = 0; j < 3; j++) {
            float s = 0.f;
            #pragma unroll
            for (int k = 0; k < 3; k++) s += W[i * 3 + k] * W[k * 3 + j];
            W2[i * 3 + j] = s;
        }
    float V[9];
    #pragma unroll
    for (int i = 0; i < 3; i++)
        #pragma unroll
        for (int j = 0; j < 3; j++) {
            float id = (i == j) ? 1.f : 0.f;
            g_pp.R[i * 3 + j] = id + A * W[i * 3 + j] + B * W2[i * 3 + j];
            V[i * 3 + j] = id + B * W[i * 3 + j] + C * W2[i * 3 + j];
        }
    g_pp.t[0] = V[0] * vx + V[1] * vy + V[2] * vz;
    g_pp.t[1] = V[3] * vx + V[4] * vy + V[5] * vz;
    g_pp.t[2] = V[6] * vx + V[7] * vy + V[8] * vz;
    g_pp.fx = K[0];
    g_pp.fy = K[4];
    g_pp.cx = K[2];
    g_pp.cy = K[5];
}

__global__ __launch_bounds__(BX, 14) void pose_kernel(
    const float* __restrict__ ref_img,
    const float* __restrict__ ref_depth,
    const float* __restrict__ trg_img,
    float* __restrict__ out,
    int H)
{
    __shared__ float st[3][TILE_W];   // trg rows v-1, v, v+1 over [u0-4, u0+131]
    __shared__ float so[BX * 7];      // output staging

    const int tid = threadIdx.x;
    const int u0  = blockIdx.x * BX;
    const int v   = blockIdx.y;
    const int u   = u0 + tid;
    const int n   = v * IMG_W + u;

    // ---- cooperative trg tile load: 3 rows x 34 float4 ----
    for (int idx = tid; idx < 3 * TILE_F4; idx += BX) {
        const int r  = idx / TILE_F4;
        const int c  = idx - r * TILE_F4;
        int gr = v + r - 1;
        gr = min(max(gr, 0), H - 1);           // clamped rows only feed unused border lanes
        const int gc = u0 - 4 + c * 4;
        float4 val = make_float4(0.f, 0.f, 0.f, 0.f);
        if (gc >= 0 && gc + 3 < IMG_W)
            val = *reinterpret_cast<const float4*>(trg_img + gr * IMG_W + gc);
        *reinterpret_cast<float4*>(&st[r][c * 4]) = val;
    }
    __syncthreads();

    // ---- uniforms ----
    const float4* pp4 = (const float4*)&g_pp;
    const float4 a0 = pp4[0], a1 = pp4[1], a2 = pp4[2], a3 = pp4[3];
    const float R00 = a0.x, R01 = a0.y, R02 = a0.z, R10 = a0.w;
    const float R11 = a1.x, R12 = a1.y, R20 = a1.z, R21 = a1.w;
    const float R22 = a2.x, t0 = a2.y, t1 = a2.z, t2v = a2.w;
    const float fx = a3.x, fy = a3.y, cx = a3.z, cy = a3.w;

    float o0 = 0.f, o1 = 0.f, o2 = 0.f, o3 = 0.f, o4 = 0.f, o5 = 0.f, o6 = 0.f;

    {
        const float z = __ldg(&ref_depth[n]);

        // ---- FROZEN index path: bit-exact vs reference ----
        const float px = __fdiv_rn(__fmul_rn((float)u - cx, z), fx);
        const float py = __fdiv_rn(__fmul_rn((float)v - cy, z), fy);
        const float pz = z;

        const float q0 = __fadd_rn(__fmaf_rn(pz, R02, __fmaf_rn(py, R01, __fmul_rn(px, R00))), t0);
        const float q1 = __fadd_rn(__fmaf_rn(pz, R12, __fmaf_rn(py, R11, __fmul_rn(px, R10))), t1);
        const float q2 = __fadd_rn(__fmaf_rn(pz, R22, __fmaf_rn(py, R21, __fmul_rn(px, R20))), t2v);

        // proj = p @ K.T : NON-FUSED mul + add (matches reference rounding)
        const float pr0 = __fadd_rn(__fmul_rn(q0, fx), __fmul_rn(q2, cx));
        const float pr1 = __fadd_rn(__fmul_rn(q1, fy), __fmul_rn(q2, cy));
        const float pr2 = q2;

        const float uw = __fdiv_rn(pr0, pr2);
        const float vw = __fdiv_rn(pr1, pr2);
        const int ui = __float2int_rz(uw);
        const int vi = __float2int_rz(vw);
        // ---- end frozen path ----

        const bool valid = (vi < H) && (ui < IMG_W) && (vi > 0) && (ui > 0);

        if (valid) {
            const float warped = __ldg(&ref_img[vi * IMG_W + ui]);
            const float tc = st[1][tid + 4];           // == trg_img[n]
            o0 = __fsub_rn(warped, tc);

            if (u >= 2 && u < IMG_W - 2 && v >= 2 && v < H - 2) {
                const int cm = tid + 3;                 // col u-1 in smem
                const float tA = st[0][cm], tB = st[0][cm + 1], tC = st[0][cm + 2];
                const float tD = st[1][cm],                     tE = st[1][cm + 2];
                const float tF = st[2][cm], tG = st[2][cm + 1], tH = st[2][cm + 2];

                const float gx = 0.125f * (tC - tA) + 0.25f * (tE - tD) + 0.125f * (tH - tF);
                const float gy = 0.125f * (tF - tA) + 0.25f * (tG - tB) + 0.125f * (tH - tC);

                const float zi  = __fdividef(1.0f, pz);     // J path: approx ok (~2^-22)
                const float xzi = px * zi;
                const float yzi = py * zi;
                const float fgx = fx * gx;                  // reference uses fx for BOTH rows
                const float fgy = fx * gy;

                o1 = -(fgx * (xzi * yzi) + fgy * (1.0f + yzi * yzi));
                o2 =   fgx * (1.0f + xzi * xzi) + fgy * (xzi * yzi);
                o3 =   fgy * xzi - fgx * yzi;
                o4 =   fgx * zi;
                o5 =   fgy * zi;
                o6 = -(fgx * xzi + fgy * yzi) * zi;
            }
        }
    }

    // ---- stage (stride-7: conflict-free) then coalesced streaming float4 stores ----
    const int si = tid * 7;
    so[si + 0] = o0; so[si + 1] = o1; so[si + 2] = o2; so[si + 3] = o3;
    so[si + 4] = o4; so[si + 5] = o5; so[si + 6] = o6;
    __syncthreads();

    float* obase = out + ((size_t)v * IMG_W + u0) * 7;   // multiple of 4 floats
    const float4* s4 = (const float4*)so;
    float4* o4p = (float4*)obase;
    __stcs(&o4p[tid], s4[tid]);
    const int i2 = tid + BX;
    if (i2 < (BX * 7) / 4) __stcs(&o4p[i2], s4[i2]);
}

extern "C" void kernel_launch(void* const* d_in, const int* in_sizes, int n_in,
                              void* d_out, int out_size) {
    const float* x         = (const float*)d_in[0];
    const float* ref_img   = (const float*)d_in[1];
    const float* ref_depth = (const float*)d_in[2];
    const float* trg_img   = (const float*)d_in[3];
    const float* K         = (const float*)d_in[4];

    const int N = in_sizes[1];          // H*W
    const int H = N / IMG_W;            // W fixed at 1920

    prep_kernel<<<1, 1>>>(x, K);
    dim3 grid(IMG_W / BX, H);
    pose_kernel<<<grid, BX>>>(ref_img, ref_depth, trg_img, (float*)d_out, H);
}

// round 9
// speedup vs baseline: 1.0833x; 1.0013x over previous
#include <cuda_runtime.h>
#include <math.h>

#define IMG_W   1920
#define BX      128
#define TILE_F4 34            // float4 per smem row: covers cols [u0-4, u0+131]
#define TILE_W  (TILE_F4 * 4)

// Params: R[9], t[3], fx, fy, cx, cy  -> 16 floats, 4x float4
struct __align__(16) PoseParams {
    float R[9];
    float t[3];
    float fx, fy, cx, cy;
};

__device__ PoseParams g_pp;

__global__ void prep_kernel(const float* __restrict__ x, const float* __restrict__ K) {
    float wx = x[0], wy = x[1], wz = x[2];
    float vx = x[3], vy = x[4], vz = x[5];
    float t2 = wx * wx + wy * wy + wz * wz;
    bool small = t2 < 1e-8f;
    float th = sqrtf(small ? 1.0f : t2);
    float A = small ? (1.0f - t2 / 6.0f) : (sinf(th) / th);
    float B = small ? (0.5f - t2 / 24.0f) : ((1.0f - cosf(th)) / (th * th));
    float C = small ? (1.0f / 6.0f - t2 / 120.0f) : ((th - sinf(th)) / (th * th * th));

    float W[9] = {0.f, -wz, wy,
                  wz, 0.f, -wx,
                  -wy, wx, 0.f};
    float W2[9];
    #pragma unroll
    for (int i = 0; i < 3; i++)
        #pragma unroll
        for (int j = 0; j < 3; j++) {
            float s = 0.f;
            #pragma unroll
            for (int k = 0; k < 3; k++) s += W[i * 3 + k] * W[k * 3 + j];
            W2[i * 3 + j] = s;
        }
    float V[9];
    #pragma unroll
    for (int i = 0; i < 3; i++)
        #pragma unroll
        for (int j = 0; j < 3; j++) {
            float id = (i == j) ? 1.f : 0.f;
            g_pp.R[i * 3 + j] = id + A * W[i * 3 + j] + B * W2[i * 3 + j];
            V[i * 3 + j] = id + B * W[i * 3 + j] + C * W2[i * 3 + j];
        }
    g_pp.t[0] = V[0] * vx + V[1] * vy + V[2] * vz;
    g_pp.t[1] = V[3] * vx + V[4] * vy + V[5] * vz;
    g_pp.t[2] = V[6] * vx + V[7] * vy + V[8] * vz;
    g_pp.fx = K[0];
    g_pp.fy = K[4];
    g_pp.cx = K[2];
    g_pp.cy = K[5];
}

__global__ __launch_bounds__(BX, 16) void pose_kernel(
    const float* __restrict__ ref_img,
    const float* __restrict__ ref_depth,
    const float* __restrict__ trg_img,
    float* __restrict__ out,
    int H)
{
    __shared__ float st[3][TILE_W];   // trg rows v-1, v, v+1 over [u0-4, u0+131]
    __shared__ float so[BX * 7];      // output staging

    const int tid = threadIdx.x;
    const int u0  = blockIdx.x * BX;
    const int v   = blockIdx.y;
    const int u   = u0 + tid;
    const int n   = v * IMG_W + u;

    // ---- cooperative trg tile load: 3 rows x 34 float4 ----
    for (int idx = tid; idx < 3 * TILE_F4; idx += BX) {
        const int r  = idx / TILE_F4;
        const int c  = idx - r * TILE_F4;
        int gr = v + r - 1;
        gr = min(max(gr, 0), H - 1);           // clamped rows only feed unused border lanes
        const int gc = u0 - 4 + c * 4;
        float4 val = make_float4(0.f, 0.f, 0.f, 0.f);
        if (gc >= 0 && gc + 3 < IMG_W)
            val = *reinterpret_cast<const float4*>(trg_img + gr * IMG_W + gc);
        *reinterpret_cast<float4*>(&st[r][c * 4]) = val;
    }
    __syncthreads();

    // ---- uniforms ----
    const float4* pp4 = (const float4*)&g_pp;
    const float4 a0 = pp4[0], a1 = pp4[1], a2 = pp4[2], a3 = pp4[3];
    const float R00 = a0.x, R01 = a0.y, R02 = a0.z, R10 = a0.w;
    const float R11 = a1.x, R12 = a1.y, R20 = a1.z, R21 = a1.w;
    const float R22 = a2.x, t0 = a2.y, t1 = a2.z, t2v = a2.w;
    const float fx = a3.x, fy = a3.y, cx = a3.z, cy = a3.w;

    float o0 = 0.f, o1 = 0.f, o2 = 0.f, o3 = 0.f, o4 = 0.f, o5 = 0.f, o6 = 0.f;

    {
        const float z = __ldg(&ref_depth[n]);

        // ---- FROZEN index path: bit-exact vs reference ----
        const float px = __fdiv_rn(__fmul_rn((float)u - cx, z), fx);
        const float py = __fdiv_rn(__fmul_rn((float)v - cy, z), fy);
        const float pz = z;

        const float q0 = __fadd_rn(__fmaf_rn(pz, R02, __fmaf_rn(py, R01, __fmul_rn(px, R00))), t0);
        const float q1 = __fadd_rn(__fmaf_rn(pz, R12, __fmaf_rn(py, R11, __fmul_rn(px, R10))), t1);
        const float q2 = __fadd_rn(__fmaf_rn(pz, R22, __fmaf_rn(py, R21, __fmul_rn(px, R20))), t2v);

        // proj = p @ K.T : NON-FUSED mul + add (matches reference rounding)
        const float pr0 = __fadd_rn(__fmul_rn(q0, fx), __fmul_rn(q2, cx));
        const float pr1 = __fadd_rn(__fmul_rn(q1, fy), __fmul_rn(q2, cy));
        const float pr2 = q2;

        const float uw = __fdiv_rn(pr0, pr2);
        const float vw = __fdiv_rn(pr1, pr2);
        const int ui = __float2int_rz(uw);
        const int vi = __float2int_rz(vw);
        // ---- end frozen path ----

        const bool valid = (vi < H) && (ui < IMG_W) && (vi > 0) && (ui > 0);

        if (valid) {
            const float warped = __ldg(&ref_img[vi * IMG_W + ui]);
            const float tc = st[1][tid + 4];           // == trg_img[n]
            o0 = __fsub_rn(warped, tc);

            if (u >= 2 && u < IMG_W - 2 && v >= 2 && v < H - 2) {
                const int cm = tid + 3;                 // col u-1 in smem
                const float tA = st[0][cm], tB = st[0][cm + 1], tC = st[0][cm + 2];
                const float tD = st[1][cm],                     tE = st[1][cm + 2];
                const float tF = st[2][cm], tG = st[2][cm + 1], tH = st[2][cm + 2];

                const float gx = 0.125f * (tC - tA) + 0.25f * (tE - tD) + 0.125f * (tH - tF);
                const float gy = 0.125f * (tF - tA) + 0.25f * (tG - tB) + 0.125f * (tH - tC);

                const float zi  = __fdividef(1.0f, pz);     // J path: approx ok (~2^-22)
                const float xzi = px * zi;
                const float yzi = py * zi;
                const float fgx = fx * gx;                  // reference uses fx for BOTH rows
                const float fgy = fx * gy;

                o1 = -(fgx * (xzi * yzi) + fgy * (1.0f + yzi * yzi));
                o2 =   fgx * (1.0f + xzi * xzi) + fgy * (xzi * yzi);
                o3 =   fgy * xzi - fgx * yzi;
                o4 =   fgx * zi;
                o5 =   fgy * zi;
                o6 = -(fgx * xzi + fgy * yzi) * zi;
            }
        }
    }

    // ---- stage (stride-7: conflict-free) then coalesced streaming float4 stores ----
    const int si = tid * 7;
    so[si + 0] = o0; so[si + 1] = o1; so[si + 2] = o2; so[si + 3] = o3;
    so[si + 4] = o4; so[si + 5] = o5; so[si + 6] = o6;
    __syncthreads();

    float* obase = out + ((size_t)v * IMG_W + u0) * 7;   // multiple of 4 floats
    const float4* s4 = (const float4*)so;
    float4* o4p = (float4*)obase;
    __stcs(&o4p[tid], s4[tid]);
    const int i2 = tid + BX;
    if (i2 < (BX * 7) / 4) __stcs(&o4p[i2], s4[i2]);
}

extern "C" void kernel_launch(void* const* d_in, const int* in_sizes, int n_in,
                              void* d_out, int out_size) {
    const float* x         = (const float*)d_in[0];
    const float* ref_img   = (const float*)d_in[1];
    const float* ref_depth = (const float*)d_in[2];
    const float* trg_img   = (const float*)d_in[3];
    const float* K         = (const float*)d_in[4];

    const int N = in_sizes[1];          // H*W
    const int H = N / IMG_W;            // W fixed at 1920

    prep_kernel<<<1, 1>>>(x, K);
    dim3 grid(IMG_W / BX, H);
    pose_kernel<<<grid, BX>>>(ref_img, ref_depth, trg_img, (float*)d_out, H);
}

// round 11
// speedup vs baseline: 1.1636x; 1.0741x over previous
#include <cuda_runtime.h>
#include <math.h>

#define IMG_W   1920
#define BX      128
#define BY      4
#define TILE_F4 34            // float4 per smem row: covers cols [u0-4, u0+131]
#define TILE_W  (TILE_F4 * 4)

// Params: R[9], t[3], fx, fy, cx, cy  -> 16 floats, 4x float4
struct __align__(16) PoseParams {
    float R[9];
    float t[3];
    float fx, fy, cx, cy;
};

__device__ PoseParams g_pp;

__global__ void prep_kernel(const float* __restrict__ x, const float* __restrict__ K) {
    float wx = x[0], wy = x[1], wz = x[2];
    float vx = x[3], vy = x[4], vz = x[5];
    float t2 = wx * wx + wy * wy + wz * wz;
    bool small = t2 < 1e-8f;
    float th = sqrtf(small ? 1.0f : t2);
    float A = small ? (1.0f - t2 / 6.0f) : (sinf(th) / th);
    float B = small ? (0.5f - t2 / 24.0f) : ((1.0f - cosf(th)) / (th * th));
    float C = small ? (1.0f / 6.0f - t2 / 120.0f) : ((th - sinf(th)) / (th * th * th));

    float W[9] = {0.f, -wz, wy,
                  wz, 0.f, -wx,
                  -wy, wx, 0.f};
    float W2[9];
    #pragma unroll
    for (int i = 0; i < 3; i++)
        #pragma unroll
        for (int j = 0; j < 3; j++) {
            float s = 0.f;
            #pragma unroll
            for (int k = 0; k < 3; k++) s += W[i * 3 + k] * W[k * 3 + j];
            W2[i * 3 + j] = s;
        }
    float V[9];
    #pragma unroll
    for (int i = 0; i < 3; i++)
        #pragma unroll
        for (int j = 0; j < 3; j++) {
            float id = (i == j) ? 1.f : 0.f;
            g_pp.R[i * 3 + j] = id + A * W[i * 3 + j] + B * W2[i * 3 + j];
            V[i * 3 + j] = id + B * W[i * 3 + j] + C * W2[i * 3 + j];
        }
    g_pp.t[0] = V[0] * vx + V[1] * vy + V[2] * vz;
    g_pp.t[1] = V[3] * vx + V[4] * vy + V[5] * vz;
    g_pp.t[2] = V[6] * vx + V[7] * vy + V[8] * vz;
    g_pp.fx = K[0];
    g_pp.fy = K[4];
    g_pp.cx = K[2];
    g_pp.cy = K[5];
}

__global__ __launch_bounds__(BX, 12) void pose_kernel(
    const float* __restrict__ ref_img,
    const float* __restrict__ ref_depth,
    const float* __restrict__ trg_img,
    float* __restrict__ out,
    int H)
{
    __shared__ float st[BY + 2][TILE_W];   // trg rows v0-1 .. v0+4
    __shared__ float so[4][32 * 7];        // per-warp output staging

    const int tid  = threadIdx.x;
    const int lane = tid & 31;
    const int wid  = tid >> 5;
    const int u0   = blockIdx.x * BX;
    const int v0   = blockIdx.y * BY;
    const int u    = u0 + tid;

    // ---- uniforms first (overlap with tile fill) ----
    const float4* pp4 = (const float4*)&g_pp;
    const float4 a0 = pp4[0], a1 = pp4[1], a2 = pp4[2], a3 = pp4[3];

    // ---- cooperative trg tile load: 6 rows x 34 float4 = 204 ----
    for (int idx = tid; idx < (BY + 2) * TILE_F4; idx += BX) {
        const int r  = idx / TILE_F4;
        const int c  = idx - r * TILE_F4;
        int gr = v0 + r - 1;
        gr = min(max(gr, 0), H - 1);           // clamped rows feed only zeroed-J border lanes
        const int gc = u0 - 4 + c * 4;
        float4 val = make_float4(0.f, 0.f, 0.f, 0.f);
        if (gc >= 0 && gc + 3 < IMG_W)
            val = *reinterpret_cast<const float4*>(trg_img + gr * IMG_W + gc);
        *reinterpret_cast<float4*>(&st[r][c * 4]) = val;
    }

    const float R00 = a0.x, R01 = a0.y, R02 = a0.z, R10 = a0.w;
    const float R11 = a1.x, R12 = a1.y, R20 = a1.z, R21 = a1.w;
    const float R22 = a2.x, t0 = a2.y, t1 = a2.z, t2v = a2.w;
    const float fx = a3.x, fy = a3.y, cx = a3.z, cy = a3.w;

    __syncthreads();

    float* sw = so[wid];
    const int si = lane * 7;
    const float4* s4 = (const float4*)sw;

    #pragma unroll 1
    for (int r = 0; r < BY; r++) {
        const int v = v0 + r;
        const int n = v * IMG_W + u;

        float o0 = 0.f, o1 = 0.f, o2 = 0.f, o3 = 0.f, o4 = 0.f, o5 = 0.f, o6 = 0.f;

        const float z = __ldg(&ref_depth[n]);

        // ---- FROZEN index path: bit-exact vs reference ----
        const float px = __fdiv_rn(__fmul_rn((float)u - cx, z), fx);
        const float py = __fdiv_rn(__fmul_rn((float)v - cy, z), fy);
        const float pz = z;

        const float q0 = __fadd_rn(__fmaf_rn(pz, R02, __fmaf_rn(py, R01, __fmul_rn(px, R00))), t0);
        const float q1 = __fadd_rn(__fmaf_rn(pz, R12, __fmaf_rn(py, R11, __fmul_rn(px, R10))), t1);
        const float q2 = __fadd_rn(__fmaf_rn(pz, R22, __fmaf_rn(py, R21, __fmul_rn(px, R20))), t2v);

        // proj = p @ K.T : NON-FUSED mul + add (matches reference rounding)
        const float pr0 = __fadd_rn(__fmul_rn(q0, fx), __fmul_rn(q2, cx));
        const float pr1 = __fadd_rn(__fmul_rn(q1, fy), __fmul_rn(q2, cy));
        const float pr2 = q2;

        const float uw = __fdiv_rn(pr0, pr2);
        const float vw = __fdiv_rn(pr1, pr2);
        const int ui = __float2int_rz(uw);
        const int vi = __float2int_rz(vw);
        // ---- end frozen path ----

        const bool valid = (vi < H) && (ui < IMG_W) && (vi > 0) && (ui > 0);

        if (valid) {
            const float warped = __ldg(&ref_img[vi * IMG_W + ui]);
            const float tc = st[r + 1][tid + 4];       // == trg_img[n]
            o0 = __fsub_rn(warped, tc);

            if (u >= 2 && u < IMG_W - 2 && v >= 2 && v < H - 2) {
                const int cm = tid + 3;                 // col u-1 in smem
                const float tA = st[r][cm],     tB = st[r][cm + 1],     tC = st[r][cm + 2];
                const float tD = st[r + 1][cm],                         tE = st[r + 1][cm + 2];
                const float tF = st[r + 2][cm], tG = st[r + 2][cm + 1], tH = st[r + 2][cm + 2];

                const float gx = 0.125f * (tC - tA) + 0.25f * (tE - tD) + 0.125f * (tH - tF);
                const float gy = 0.125f * (tF - tA) + 0.25f * (tG - tB) + 0.125f * (tH - tC);

                const float zi  = __fdividef(1.0f, pz);     // J path: approx ok (~2^-22)
                const float xzi = px * zi;
                const float yzi = py * zi;
                const float fgx = fx * gx;                  // reference uses fx for BOTH rows
                const float fgy = fx * gy;

                o1 = -(fgx * (xzi * yzi) + fgy * (1.0f + yzi * yzi));
                o2 =   fgx * (1.0f + xzi * xzi) + fgy * (xzi * yzi);
                o3 =   fgy * xzi - fgx * yzi;
                o4 =   fgx * zi;
                o5 =   fgy * zi;
                o6 = -(fgx * xzi + fgy * yzi) * zi;
            }
        }

        // ---- per-warp staging (stride-7: conflict-free), warp-scoped sync ----
        sw[si + 0] = o0; sw[si + 1] = o1; sw[si + 2] = o2; sw[si + 3] = o3;
        sw[si + 4] = o4; sw[si + 5] = o5; sw[si + 6] = o6;
        __syncwarp();

        // warp's 32 pixels -> 224 contiguous floats = 56 float4, 16B-aligned
        float4* o4p = (float4*)(out + ((size_t)v * IMG_W + u0 + 32 * wid) * 7);
        __stcs(&o4p[lane], s4[lane]);
        const int i2 = lane + 32;
        if (i2 < 56) __stcs(&o4p[i2], s4[i2]);
        __syncwarp();    // all lanes done reading sw before next row overwrites
    }
}

extern "C" void kernel_launch(void* const* d_in, const int* in_sizes, int n_in,
                              void* d_out, int out_size) {
    const float* x         = (const float*)d_in[0];
    const float* ref_img   = (const float*)d_in[1];
    const float* ref_depth = (const float*)d_in[2];
    const float* trg_img   = (const float*)d_in[3];
    const float* K         = (const float*)d_in[4];

    const int N = in_sizes[1];          // H*W
    const int H = N / IMG_W;            // W fixed at 1920; H=1080 divisible by BY=4

    prep_kernel<<<1, 1>>>(x, K);
    dim3 grid(IMG_W / BX, H / BY);
    pose_kernel<<<grid, BX>>>(ref_img, ref_depth, trg_img, (float*)d_out, H);
}

// round 12
// speedup vs baseline: 1.1751x; 1.0099x over previous
#include <cuda_runtime.h>
#include <math.h>

#define IMG_W   1920
#define BX      128
#define BY      4
#define TILE_F4 34            // float4 per smem row: covers cols [u0-4, u0+131]
#define TILE_W  (TILE_F4 * 4)

// Params: R[9], t[3], fx, fy, cx, cy  -> 16 floats, 4x float4
struct __align__(16) PoseParams {
    float R[9];
    float t[3];
    float fx, fy, cx, cy;
};

__device__ PoseParams g_pp;

__global__ void prep_kernel(const float* __restrict__ x, const float* __restrict__ K) {
    float wx = x[0], wy = x[1], wz = x[2];
    float vx = x[3], vy = x[4], vz = x[5];
    float t2 = wx * wx + wy * wy + wz * wz;
    bool small = t2 < 1e-8f;
    float th = sqrtf(small ? 1.0f : t2);
    float A = small ? (1.0f - t2 / 6.0f) : (sinf(th) / th);
    float B = small ? (0.5f - t2 / 24.0f) : ((1.0f - cosf(th)) / (th * th));
    float C = small ? (1.0f / 6.0f - t2 / 120.0f) : ((th - sinf(th)) / (th * th * th));

    float W[9] = {0.f, -wz, wy,
                  wz, 0.f, -wx,
                  -wy, wx, 0.f};
    float W2[9];
    #pragma unroll
    for (int i = 0; i < 3; i++)
        #pragma unroll
        for (int j = 0; j < 3; j++) {
            float s = 0.f;
            #pragma unroll
            for (int k = 0; k < 3; k++) s += W[i * 3 + k] * W[k * 3 + j];
            W2[i * 3 + j] = s;
        }
    float V[9];
    #pragma unroll
    for (int i = 0; i < 3; i++)
        #pragma unroll
        for (int j = 0; j < 3; j++) {
            float id = (i == j) ? 1.f : 0.f;
            g_pp.R[i * 3 + j] = id + A * W[i * 3 + j] + B * W2[i * 3 + j];
            V[i * 3 + j] = id + B * W[i * 3 + j] + C * W2[i * 3 + j];
        }
    g_pp.t[0] = V[0] * vx + V[1] * vy + V[2] * vz;
    g_pp.t[1] = V[3] * vx + V[4] * vy + V[5] * vz;
    g_pp.t[2] = V[6] * vx + V[7] * vy + V[8] * vz;
    g_pp.fx = K[0];
    g_pp.fy = K[4];
    g_pp.cx = K[2];
    g_pp.cy = K[5];
}

__global__ __launch_bounds__(BX, 12) void pose_kernel(
    const float* __restrict__ ref_img,
    const float* __restrict__ ref_depth,
    const float* __restrict__ trg_img,
    float* __restrict__ out,
    int H)
{
    __shared__ float st[BY + 2][TILE_W];   // trg rows v0-1 .. v0+4
    __shared__ float so[4][32 * 7];        // per-warp output staging

    const int tid  = threadIdx.x;
    const int lane = tid & 31;
    const int wid  = tid >> 5;
    const int u0   = blockIdx.x * BX;
    const int v0   = blockIdx.y * BY;
    const int u    = u0 + tid;

    // ---- uniforms + first depth row issued early (overlap with tile fill) ----
    const float4* pp4 = (const float4*)&g_pp;
    const float4 a0 = pp4[0], a1 = pp4[1], a2 = pp4[2], a3 = pp4[3];

    const float* dp = ref_depth + (size_t)v0 * IMG_W + u;
    float znext = __ldg(dp);               // row v0 depth, in flight across the barrier

    // ---- cooperative trg tile load: 6 rows x 34 float4 = 204 ----
    for (int idx = tid; idx < (BY + 2) * TILE_F4; idx += BX) {
        const int r  = idx / TILE_F4;
        const int c  = idx - r * TILE_F4;
        int gr = v0 + r - 1;
        gr = min(max(gr, 0), H - 1);           // clamped rows feed only zeroed-J border lanes
        const int gc = u0 - 4 + c * 4;
        float4 val = make_float4(0.f, 0.f, 0.f, 0.f);
        if (gc >= 0 && gc + 3 < IMG_W)
            val = *reinterpret_cast<const float4*>(trg_img + gr * IMG_W + gc);
        *reinterpret_cast<float4*>(&st[r][c * 4]) = val;
    }

    const float R00 = a0.x, R01 = a0.y, R02 = a0.z, R10 = a0.w;
    const float R11 = a1.x, R12 = a1.y, R20 = a1.z, R21 = a1.w;
    const float R22 = a2.x, t0 = a2.y, t1 = a2.z, t2v = a2.w;
    const float fx = a3.x, fy = a3.y, cx = a3.z, cy = a3.w;

    __syncthreads();

    float* sw = so[wid];
    const int si = lane * 7;
    const float4* s4 = (const float4*)sw;

    #pragma unroll 1
    for (int r = 0; r < BY; r++) {
        const int v = v0 + r;

        const float z = znext;                         // this row's depth (prefetched)
        if (r + 1 < BY)
            znext = __ldg(dp + (size_t)(r + 1) * IMG_W);   // overlap next row's LDG

        float o0 = 0.f, o1 = 0.f, o2 = 0.f, o3 = 0.f, o4 = 0.f, o5 = 0.f, o6 = 0.f;

        // ---- FROZEN index path: bit-exact vs reference ----
        const float px = __fdiv_rn(__fmul_rn((float)u - cx, z), fx);
        const float py = __fdiv_rn(__fmul_rn((float)v - cy, z), fy);
        const float pz = z;

        const float q0 = __fadd_rn(__fmaf_rn(pz, R02, __fmaf_rn(py, R01, __fmul_rn(px, R00))), t0);
        const float q1 = __fadd_rn(__fmaf_rn(pz, R12, __fmaf_rn(py, R11, __fmul_rn(px, R10))), t1);
        const float q2 = __fadd_rn(__fmaf_rn(pz, R22, __fmaf_rn(py, R21, __fmul_rn(px, R20))), t2v);

        // proj = p @ K.T : NON-FUSED mul + add (matches reference rounding)
        const float pr0 = __fadd_rn(__fmul_rn(q0, fx), __fmul_rn(q2, cx));
        const float pr1 = __fadd_rn(__fmul_rn(q1, fy), __fmul_rn(q2, cy));
        const float pr2 = q2;

        const float uw = __fdiv_rn(pr0, pr2);
        const float vw = __fdiv_rn(pr1, pr2);
        const int ui = __float2int_rz(uw);
        const int vi = __float2int_rz(vw);
        // ---- end frozen path ----

        const bool valid = (vi < H) && (ui < IMG_W) && (vi > 0) && (ui > 0);

        if (valid) {
            const float warped = __ldg(&ref_img[vi * IMG_W + ui]);
            const float tc = st[r + 1][tid + 4];       // == trg_img[v*W+u]
            o0 = __fsub_rn(warped, tc);

            if (u >= 2 && u < IMG_W - 2 && v >= 2 && v < H - 2) {
                const int cm = tid + 3;                 // col u-1 in smem
                const float tA = st[r][cm],     tB = st[r][cm + 1],     tC = st[r][cm + 2];
                const float tD = st[r + 1][cm],                         tE = st[r + 1][cm + 2];
                const float tF = st[r + 2][cm], tG = st[r + 2][cm + 1], tH = st[r + 2][cm + 2];

                const float gx = 0.125f * (tC - tA) + 0.25f * (tE - tD) + 0.125f * (tH - tF);
                const float gy = 0.125f * (tF - tA) + 0.25f * (tG - tB) + 0.125f * (tH - tC);

                const float zi  = __fdividef(1.0f, pz);     // J path: approx ok (~2^-22)
                const float xzi = px * zi;
                const float yzi = py * zi;
                const float fgx = fx * gx;                  // reference uses fx for BOTH rows
                const float fgy = fx * gy;

                o1 = -(fgx * (xzi * yzi) + fgy * (1.0f + yzi * yzi));
                o2 =   fgx * (1.0f + xzi * xzi) + fgy * (xzi * yzi);
                o3 =   fgy * xzi - fgx * yzi;
                o4 =   fgx * zi;
                o5 =   fgy * zi;
                o6 = -(fgx * xzi + fgy * yzi) * zi;
            }
        }

        // ---- per-warp staging (stride-7: conflict-free), warp-scoped sync ----
        sw[si + 0] = o0; sw[si + 1] = o1; sw[si + 2] = o2; sw[si + 3] = o3;
        sw[si + 4] = o4; sw[si + 5] = o5; sw[si + 6] = o6;
        __syncwarp();

        // warp's 32 pixels -> 224 contiguous floats = 56 float4, 16B-aligned
        float4* o4p = (float4*)(out + ((size_t)v * IMG_W + u0 + 32 * wid) * 7);
        __stcs(&o4p[lane], s4[lane]);
        const int i2 = lane + 32;
        if (i2 < 56) __stcs(&o4p[i2], s4[i2]);
        __syncwarp();    // all lanes done reading sw before next row overwrites
    }
}

extern "C" void kernel_launch(void* const* d_in, const int* in_sizes, int n_in,
                              void* d_out, int out_size) {
    const float* x         = (const float*)d_in[0];
    const float* ref_img   = (const float*)d_in[1];
    const float* ref_depth = (const float*)d_in[2];
    const float* trg_img   = (const float*)d_in[3];
    const float* K         = (const float*)d_in[4];

    const int N = in_sizes[1];          // H*W
    const int H = N / IMG_W;            // W fixed at 1920; H=1080 divisible by BY=4

    prep_kernel<<<1, 1>>>(x, K);
    dim3 grid(IMG_W / BX, H / BY);
    pose_kernel<<<grid, BX>>>(ref_img, ref_depth, trg_img, (float*)d_out, H);
}